// round 15
// baseline (speedup 1.0000x reference)
#include <cuda_runtime.h>
#include <cuda_bf16.h>

// DETR post-processor, SINGLE persistent kernel (expected shape):
//   410 CTAs x 512 thr (all wave-1).
//   Phase 1 (all CTAs): stream segments bid, bid+410, ... (2048 total, 8 per
//     batch x 2500 float4). Software-pipelined: each iteration issues
//     prefetch.global.L2 for the NEXT segment's lines before screening the
//     current one, so DRAM stays busy across the barrier/flush tail.
//     FMNMX screen at t=2.576 -> smem buffer via smem atomics; ONE global
//     atomic reserves a g_cand block; coalesced flush; threadfence +
//     per-batch done-increment. 3 barriers per segment.
//   Phase 2 (CTAs 0..255, AFTER all own streaming): prefetch batch's boxes
//     to smem (overlaps spin), spin on g_done[batch]==8, acquire fence, then
//     256 threads bitonic-sort the <=512 candidates (2/thread: shfl j<=16,
//     local j=32, smem j>=64) and decode the top-300 from registers.
//   Deadlock-free: waiting CTAs <= 256 < 296 min capacity. Counters
//   self-reset for graph replay. Exact histogram fallback if count outside
//   [300,512] (lambda=400, sigma=20). Generic shape -> 2-kernel pipeline.

#define NCLS    80
#define NQ      1000
#define NPB     80000
#define NF4B    20000          // float4 per batch
#define NB      256
#define TOPK    300
#define CAP     512
#define THR     2.576f
#define SEGS    8              // segments per batch
#define NSEG    (NB * SEGS)    // 2048 segments
#define SEGF4   2500           // float4 per segment
#define SCTA    512
#define RT      256            // sorter active threads
#define GRID_P  410            // persistent grid (410*5 = 2050 >= 2048)
#define BUFCAP  384            // smem candidate buffer (segment lambda=50)
#define GPAD    32             // counter stride (128B) -> spread LTS slices
#define NHIST   4096

__device__ unsigned long long g_cand[NB][CAP];
__device__ int g_cnt[NB * GPAD];
__device__ int g_done[NB * GPAD];

struct SortSmem {
    union {
        unsigned long long s[CAP];      // 4KB: collect buf / sort exchange
        unsigned hist[NHIST];           // 16KB: fallback histogram
    } u;
    int c;
    int base;
    unsigned tk;
};

__device__ __forceinline__ unsigned fkey(float f) {
    unsigned u = __float_as_uint(f);
    return (u & 0x80000000u) ? ~u : (u | 0x80000000u);  // monotonic float->uint
}
__device__ __forceinline__ float key2f(unsigned k) {
    return (k & 0x80000000u) ? __uint_as_float(k & 0x7fffffffu)
                             : __uint_as_float(~k);
}
__device__ __forceinline__ unsigned long long pack(float val, unsigned loc) {
    return ((unsigned long long)fkey(val) << 32) | (unsigned)(0xFFFFFFFFu - loc);
}
__device__ __forceinline__ void l2pf(const void* p) {
    asm volatile("prefetch.global.L2 [%0];" :: "l"(p));
}

// ---- bitonic helpers (element index i, phase j, block k) ----
__device__ __forceinline__ unsigned long long upick(
    unsigned long long v, unsigned long long o, int i, int j, int k)
{
    const bool keep_max = (((i & j) == 0) == ((i & k) == 0));
    const unsigned long long mx = v > o ? v : o;
    const unsigned long long mn = v > o ? o : v;
    return keep_max ? mx : mn;
}
__device__ __forceinline__ unsigned long long ushfl(
    unsigned long long v, int i, int j, int k)
{
    const unsigned long long o = __shfl_xor_sync(0xFFFFFFFFu, v, j);
    return upick(v, o, i, j, k);
}
__device__ __forceinline__ void ulocal32(
    unsigned long long& r0, unsigned long long& r1, int i0, int k)
{
    const bool desc = ((i0 & k) == 0);
    const unsigned long long hi = r0 > r1 ? r0 : r1;
    const unsigned long long lo = r0 > r1 ? r1 : r0;
    r0 = desc ? hi : lo;
    r1 = desc ? lo : hi;
}

// ---- rank body: 256 threads, sort <=512 candidates of batch n, emit ----
__device__ void rank_body(SortSmem* sm, const float4* __restrict__ sbx,
                          const float4* __restrict__ lg,
                          const int*    __restrict__ sizes,
                          float*        __restrict__ out,
                          int n, int tid)
{
    const int l  = tid & 31;
    const int w  = tid >> 5;            // 8 warps
    const int i0 = w * 64 + l;          // slots i0, i0+32 cover 0..511
    const int i1 = i0 + 32;

    // issue count + candidate loads concurrently (stale tails masked below)
    const int cnt = g_cnt[n * GPAD];
    unsigned long long c0 = g_cand[n][i0];
    unsigned long long c1 = g_cand[n][i1];
    const bool ok = (cnt >= TOPK && cnt <= CAP);
    unsigned long long r0 = (ok && i0 < cnt) ? c0 : 0ULL;
    unsigned long long r1 = (ok && i1 < cnt) ? c1 : 0ULL;

    __syncthreads();                    // all cnt/cand reads done
    if (tid == 0) {                     // reset for next graph replay
        g_cnt[n * GPAD]  = 0;
        g_done[n * GPAD] = 0;
    }

    if (!ok) {
        // ---- exact fallback: histogram threshold + recollect ----
        const float4* base = lg + (size_t)n * (NPB / 4);
        for (int i = tid; i < NHIST; i += RT) sm->u.hist[i] = 0u;
        if (tid == 0) sm->c = 0;
        __syncthreads();
        for (int i = tid; i < NPB / 4; i += RT) {
            float4 x = base[i];
            atomicAdd(&sm->u.hist[fkey(x.x) >> 20], 1u);
            atomicAdd(&sm->u.hist[fkey(x.y) >> 20], 1u);
            atomicAdd(&sm->u.hist[fkey(x.z) >> 20], 1u);
            atomicAdd(&sm->u.hist[fkey(x.w) >> 20], 1u);
        }
        __syncthreads();
        if (tid == 0) {
            unsigned acc = 0; int b = NHIST - 1;
            for (; b > 0; --b) { acc += sm->u.hist[b]; if (acc >= TOPK) break; }
            sm->tk = (unsigned)b << 20;
        }
        __syncthreads();
        const unsigned tk = sm->tk;
        for (int i = tid; i < CAP; i += RT) sm->u.s[i] = 0ULL;
        __syncthreads();
        for (int i = tid; i < NPB / 4; i += RT) {
            float4 x = base[i];
            const float e[4] = {x.x, x.y, x.z, x.w};
            #pragma unroll
            for (int j = 0; j < 4; j++) {
                unsigned kk = fkey(e[j]);
                if (kk >= tk) {
                    int p = atomicAdd(&sm->c, 1);
                    if (p < CAP)
                        sm->u.s[p] = ((unsigned long long)kk << 32) |
                                     (unsigned)(0xFFFFFFFFu - (unsigned)(4 * i + j));
                }
            }
        }
        __syncthreads();
        r0 = sm->u.s[i0];
        r1 = sm->u.s[i1];
        // safe: each thread reads only its own slots; the sort's first smem
        // write to those slots is by this same thread
    }

    // ---- bitonic sort, descending, 512 elems, 2 per thread ----
    #pragma unroll
    for (int k = 2; k <= 32; k <<= 1)
        #pragma unroll
        for (int j = k >> 1; j >= 1; j >>= 1) {
            r0 = ushfl(r0, i0, j, k);
            r1 = ushfl(r1, i1, j, k);
        }
    ulocal32(r0, r1, i0, 64);
    #pragma unroll
    for (int j = 16; j >= 1; j >>= 1) {
        r0 = ushfl(r0, i0, j, 64);
        r1 = ushfl(r1, i1, j, 64);
    }
    #pragma unroll
    for (int k = 128; k <= CAP; k <<= 1) {
        sm->u.s[i0] = r0; sm->u.s[i1] = r1;
        __syncthreads();
        #pragma unroll
        for (int j = k >> 1; j >= 64; j >>= 1) {
            const unsigned long long o0 = sm->u.s[i0 ^ j];
            const unsigned long long o1 = sm->u.s[i1 ^ j];
            r0 = upick(r0, o0, i0, j, k);
            r1 = upick(r1, o1, i1, j, k);
            __syncthreads();                       // all reads done
            if (j > 64) { sm->u.s[i0] = r0; sm->u.s[i1] = r1; __syncthreads(); }
        }
        ulocal32(r0, r1, i0, k);
        #pragma unroll
        for (int j = 16; j >= 1; j >>= 1) {
            r0 = ushfl(r0, i0, j, k);
            r1 = ushfl(r1, i1, j, k);
        }
    }

    // ---- epilogue: slots < 300 decode, boxes from smem ----
    const float fx = (float)sizes[1];
    const float fy = (float)sizes[0];
    #pragma unroll
    for (int e = 0; e < 2; e++) {
        const int slot = e ? i1 : i0;
        if (slot < TOPK) {
            const unsigned long long pk = e ? r1 : r0;
            const unsigned key  = (unsigned)(pk >> 32);
            const unsigned flat = 0xFFFFFFFFu - (unsigned)(pk & 0xFFFFFFFFu);
            const float lv    = key2f(key);
            const float score = 1.0f / (1.0f + __expf(-lv));
            const unsigned q   = flat / (unsigned)NCLS;
            const unsigned lbl = flat - q * (unsigned)NCLS;
            const float4 b = sbx[q];                       // [cx, cy, w, h]
            float2* o = reinterpret_cast<float2*>(out + ((size_t)n * TOPK + slot) * 6);
            o[0] = make_float2((float)lbl, score);
            o[1] = make_float2((b.x - 0.5f * b.z) * fx, (b.y - 0.5f * b.w) * fy);
            o[2] = make_float2(b.z * fx, b.w * fy);
        }
    }
}

// ---- persistent fused kernel: stream all own segments, then sort ----
__global__ __launch_bounds__(SCTA, 3)
void scan_rank(const float4* __restrict__ lg,
               const float4* __restrict__ bx,
               const int*    __restrict__ sizes,
               float*        __restrict__ out)
{
    __shared__ SortSmem sm;
    __shared__ float4 sbx[NQ];          // 16KB: prefetched boxes (sorters)

    const int bid = blockIdx.x;
    const int t   = threadIdx.x;
    const bool has5 = (t < (int)(SEGF4 - 4 * SCTA));   // t < 452

    if (t == 0) sm.c = 0;
    __syncthreads();

    // ========== phase 1: stream segments bid, bid+G, ... ==========
    for (unsigned sid = (unsigned)bid; sid < (unsigned)NSEG; sid += gridDim.x) {
        const unsigned n   = sid >> 3;
        const unsigned seg = sid & 7u;
        const unsigned f4base = n * (unsigned)NF4B + seg * (unsigned)SEGF4;

        // issue current segment's loads (front-batched, MLP=5)
        float4 v[5];
        #pragma unroll
        for (int k = 0; k < 4; k++) v[k] = lg[f4base + t + k * SCTA];
        if (has5) v[4] = lg[f4base + t + 4 * SCTA];

        // prefetch NEXT segment into L2: keeps DRAM busy through the
        // screen/barrier/flush tail below (no registers consumed)
        const unsigned nsid = sid + gridDim.x;
        if (nsid < (unsigned)NSEG) {
            const float4* np = lg + (size_t)(nsid >> 3) * NF4B
                                  + (size_t)(nsid & 7u) * SEGF4;
            #pragma unroll
            for (int k = 0; k < 4; k++) l2pf(np + t + k * SCTA);
            if (has5) l2pf(np + t + 4 * SCTA);
        }

        #pragma unroll
        for (int k = 0; k < 5; k++) {
            if (k == 4 && !has5) continue;
            const float4 x = v[k];
            if (fmaxf(fmaxf(x.x, x.y), fmaxf(x.z, x.w)) > THR) {  // ~2%
                const unsigned loc0 = (seg * (unsigned)SEGF4 + (unsigned)t + (unsigned)k * SCTA) * 4u;
                if (x.x > THR) { int p = atomicAdd(&sm.c, 1); if (p < BUFCAP) sm.u.s[p] = pack(x.x, loc0 + 0u); }
                if (x.y > THR) { int p = atomicAdd(&sm.c, 1); if (p < BUFCAP) sm.u.s[p] = pack(x.y, loc0 + 1u); }
                if (x.z > THR) { int p = atomicAdd(&sm.c, 1); if (p < BUFCAP) sm.u.s[p] = pack(x.z, loc0 + 2u); }
                if (x.w > THR) { int p = atomicAdd(&sm.c, 1); if (p < BUFCAP) sm.u.s[p] = pack(x.w, loc0 + 3u); }
            }
        }
        __syncthreads();                          // screen done, cnt stable

        const int cnt = sm.c;
        if (t == 0) {
            if (cnt > BUFCAP) {       // overflow -> poison count, force fallback
                atomicAdd(&g_cnt[n * GPAD], 1000000);
                sm.base = -1;
            } else {
                sm.base = atomicAdd(&g_cnt[n * GPAD], cnt);
            }
        }
        __syncthreads();                          // base broadcast

        const int base = sm.base;
        if (base >= 0) {
            for (int i = t; i < cnt; i += SCTA) {
                const int p = base + i;
                if (p < CAP) g_cand[n][p] = sm.u.s[i];   // >CAP -> fallback
            }
        }
        if (t == 0) sm.c = 0;                     // reset for next segment
                                                  // (cnt latched, base done)
        __syncthreads();                          // flush done + sm reuse safe
        if (t == 0) {
            __threadfence();                      // publish flush + count
            atomicAdd(&g_done[n * GPAD], 1);      // signal batch readiness
        }
    }

    // ========== phase 2: CTAs 0..255 sort their batch ==========
    if (bid >= NB) return;
    const int n = bid;

    // prefetch boxes (independent of candidates; overlaps the spin)
    for (int i = t; i < NQ; i += SCTA)
        sbx[i] = bx[(size_t)n * NQ + i];

    if (t == 0) {
        volatile int* done = &g_done[n * GPAD];
        while (*done < SEGS) __nanosleep(64);
        __threadfence();                          // acquire all segments' data
    }
    __syncthreads();                              // all 512 still active here
    if (t >= RT) return;                          // sort uses 256 threads

    rank_body(&sm, sbx, lg, sizes, out, n, t);
}

// ================= generic-shape pipeline =================

__global__ __launch_bounds__(SCTA)
void scan_generic(const float4* __restrict__ lg, int total_f4)
{
    const unsigned S = gridDim.x * (unsigned)SCTA;
    for (unsigned i = blockIdx.x * SCTA + threadIdx.x; i < (unsigned)total_f4; i += S) {
        const float4 x = lg[i];
        if (fmaxf(fmaxf(x.x, x.y), fmaxf(x.z, x.w)) > THR) {
            const float e[4] = {x.x, x.y, x.z, x.w};
            #pragma unroll
            for (int j = 0; j < 4; j++) {
                if (e[j] > THR) {
                    const unsigned flat = i * 4u + (unsigned)j;
                    const unsigned n    = flat / (unsigned)NPB;
                    if (n < (unsigned)NB) {
                        const int p = atomicAdd(&g_cnt[n * GPAD], 1);
                        if (p < CAP)
                            g_cand[n][p] = pack(e[j], flat - n * (unsigned)NPB);
                    }
                }
            }
        }
    }
}

__global__ __launch_bounds__(RT)
void rank_kernel(const float4* __restrict__ lg,
                 const float4* __restrict__ bx,
                 const int*    __restrict__ sizes,
                 float*        __restrict__ out)
{
    __shared__ SortSmem sm;
    __shared__ float4 sbx[NQ];
    const int n = blockIdx.x;
    for (int i = threadIdx.x; i < NQ; i += RT)
        sbx[i] = bx[(size_t)n * NQ + i];
    __syncthreads();
    rank_body(&sm, sbx, lg, sizes, out, n, threadIdx.x);
}

extern "C" void kernel_launch(void* const* d_in, const int* in_sizes, int n_in,
                              void* d_out, int out_size)
{
    const float* logits = (const float*)d_in[0];
    const float* boxes  = (const float*)d_in[1];
    const int*   sizes  = (const int*)d_in[2];
    const int total     = in_sizes[0];
    const int N         = total / NPB;

    if (total == NB * NPB) {
        scan_rank<<<GRID_P, SCTA>>>((const float4*)logits,
                                    (const float4*)boxes, sizes,
                                    (float*)d_out);
    } else {
        const int total_f4 = total / 4;
        int grid = (total_f4 + SCTA - 1) / SCTA;
        if (grid > 2048) grid = 2048;
        if (grid < 1) grid = 1;
        scan_generic<<<grid, SCTA>>>((const float4*)logits, total_f4);
        rank_kernel<<<N, RT>>>((const float4*)logits, (const float4*)boxes,
                               sizes, (float*)d_out);
    }
}

// round 16
// speedup vs baseline: 1.1001x; 1.1001x over previous
#include <cuda_runtime.h>
#include <cuda_bf16.h>

// DETR post-processor, SINGLE persistent kernel (expected shape):
//   410 CTAs x 512 thr (all wave-1).
//   Phase 1 (all CTAs): stream segments bid, bid+410, ... (2048 total, 8 per
//     batch x 2500 float4): FMNMX screen at t=2.576 -> smem buffer via smem
//     atomics; ONE global atomic reserves a g_cand block; coalesced flush;
//     then RELEASE-scoped red.gpu on the per-batch done counter (NO
//     __threadfence -- GPU-scope MEMBAR under saturated DRAM queues is what
//     capped every fused variant at 2-3 TB/s; release orders only this CTA's
//     prior writes at the L2 point).
//   Phase 2 (CTAs 0..255, AFTER all own streaming): prefetch batch's boxes
//     to smem, poll g_done[batch] with ld.acquire.gpu (+nanosleep), then
//     256 threads bitonic-sort the <=512 candidates (2/thread: shfl j<=16,
//     local j=32, smem j>=64) and decode the top-300 from registers.
//   Deadlock-free: waiting CTAs <= 256 < 296 min capacity. Counters
//   self-reset for graph replay. Exact histogram fallback if count outside
//   [300,512] (lambda=400, sigma=20). Generic shape -> 2-kernel pipeline.

#define NCLS    80
#define NQ      1000
#define NPB     80000
#define NF4B    20000          // float4 per batch
#define NB      256
#define TOPK    300
#define CAP     512
#define THR     2.576f
#define SEGS    8              // segments per batch
#define NSEG    (NB * SEGS)    // 2048 segments
#define SEGF4   2500           // float4 per segment
#define SCTA    512
#define RT      256            // sorter active threads
#define GRID_P  410            // persistent grid (410*5 = 2050 >= 2048)
#define BUFCAP  384            // smem candidate buffer (segment lambda=50)
#define GPAD    32             // counter stride (128B) -> spread LTS slices
#define NHIST   4096

__device__ unsigned long long g_cand[NB][CAP];
__device__ int g_cnt[NB * GPAD];
__device__ int g_done[NB * GPAD];

struct SortSmem {
    union {
        unsigned long long s[CAP];      // 4KB: collect buf / sort exchange
        unsigned hist[NHIST];           // 16KB: fallback histogram
    } u;
    int c;
    int base;
    unsigned tk;
};

__device__ __forceinline__ unsigned fkey(float f) {
    unsigned u = __float_as_uint(f);
    return (u & 0x80000000u) ? ~u : (u | 0x80000000u);  // monotonic float->uint
}
__device__ __forceinline__ float key2f(unsigned k) {
    return (k & 0x80000000u) ? __uint_as_float(k & 0x7fffffffu)
                             : __uint_as_float(~k);
}
__device__ __forceinline__ unsigned long long pack(float val, unsigned loc) {
    return ((unsigned long long)fkey(val) << 32) | (unsigned)(0xFFFFFFFFu - loc);
}

// release-scoped add: publishes this CTA's prior writes (after syncthreads)
// without a chip-wide MEMBAR drain
__device__ __forceinline__ void done_release_add(int* p) {
    asm volatile("red.release.gpu.global.add.s32 [%0], %1;"
                 :: "l"(p), "r"(1) : "memory");
}
__device__ __forceinline__ int done_acquire_ld(const int* p) {
    int v;
    asm volatile("ld.acquire.gpu.global.s32 %0, [%1];"
                 : "=r"(v) : "l"(p) : "memory");
    return v;
}

// ---- bitonic helpers (element index i, phase j, block k) ----
__device__ __forceinline__ unsigned long long upick(
    unsigned long long v, unsigned long long o, int i, int j, int k)
{
    const bool keep_max = (((i & j) == 0) == ((i & k) == 0));
    const unsigned long long mx = v > o ? v : o;
    const unsigned long long mn = v > o ? o : v;
    return keep_max ? mx : mn;
}
__device__ __forceinline__ unsigned long long ushfl(
    unsigned long long v, int i, int j, int k)
{
    const unsigned long long o = __shfl_xor_sync(0xFFFFFFFFu, v, j);
    return upick(v, o, i, j, k);
}
__device__ __forceinline__ void ulocal32(
    unsigned long long& r0, unsigned long long& r1, int i0, int k)
{
    const bool desc = ((i0 & k) == 0);
    const unsigned long long hi = r0 > r1 ? r0 : r1;
    const unsigned long long lo = r0 > r1 ? r1 : r0;
    r0 = desc ? hi : lo;
    r1 = desc ? lo : hi;
}

// ---- rank body: 256 threads, sort <=512 candidates of batch n, emit ----
__device__ void rank_body(SortSmem* sm, const float4* __restrict__ sbx,
                          const float4* __restrict__ lg,
                          const int*    __restrict__ sizes,
                          float*        __restrict__ out,
                          int n, int tid)
{
    const int l  = tid & 31;
    const int w  = tid >> 5;            // 8 warps
    const int i0 = w * 64 + l;          // slots i0, i0+32 cover 0..511
    const int i1 = i0 + 32;

    // issue count + candidate loads concurrently (stale tails masked below)
    const int cnt = g_cnt[n * GPAD];
    unsigned long long c0 = g_cand[n][i0];
    unsigned long long c1 = g_cand[n][i1];
    const bool ok = (cnt >= TOPK && cnt <= CAP);
    unsigned long long r0 = (ok && i0 < cnt) ? c0 : 0ULL;
    unsigned long long r1 = (ok && i1 < cnt) ? c1 : 0ULL;

    __syncthreads();                    // all cnt/cand reads done
    if (tid == 0) {                     // reset for next graph replay
        g_cnt[n * GPAD]  = 0;
        g_done[n * GPAD] = 0;
    }

    if (!ok) {
        // ---- exact fallback: histogram threshold + recollect ----
        const float4* base = lg + (size_t)n * (NPB / 4);
        for (int i = tid; i < NHIST; i += RT) sm->u.hist[i] = 0u;
        if (tid == 0) sm->c = 0;
        __syncthreads();
        for (int i = tid; i < NPB / 4; i += RT) {
            float4 x = base[i];
            atomicAdd(&sm->u.hist[fkey(x.x) >> 20], 1u);
            atomicAdd(&sm->u.hist[fkey(x.y) >> 20], 1u);
            atomicAdd(&sm->u.hist[fkey(x.z) >> 20], 1u);
            atomicAdd(&sm->u.hist[fkey(x.w) >> 20], 1u);
        }
        __syncthreads();
        if (tid == 0) {
            unsigned acc = 0; int b = NHIST - 1;
            for (; b > 0; --b) { acc += sm->u.hist[b]; if (acc >= TOPK) break; }
            sm->tk = (unsigned)b << 20;
        }
        __syncthreads();
        const unsigned tk = sm->tk;
        for (int i = tid; i < CAP; i += RT) sm->u.s[i] = 0ULL;
        __syncthreads();
        for (int i = tid; i < NPB / 4; i += RT) {
            float4 x = base[i];
            const float e[4] = {x.x, x.y, x.z, x.w};
            #pragma unroll
            for (int j = 0; j < 4; j++) {
                unsigned kk = fkey(e[j]);
                if (kk >= tk) {
                    int p = atomicAdd(&sm->c, 1);
                    if (p < CAP)
                        sm->u.s[p] = ((unsigned long long)kk << 32) |
                                     (unsigned)(0xFFFFFFFFu - (unsigned)(4 * i + j));
                }
            }
        }
        __syncthreads();
        r0 = sm->u.s[i0];
        r1 = sm->u.s[i1];
        // safe: each thread reads only its own slots; the sort's first smem
        // write to those slots is by this same thread
    }

    // ---- bitonic sort, descending, 512 elems, 2 per thread ----
    #pragma unroll
    for (int k = 2; k <= 32; k <<= 1)
        #pragma unroll
        for (int j = k >> 1; j >= 1; j >>= 1) {
            r0 = ushfl(r0, i0, j, k);
            r1 = ushfl(r1, i1, j, k);
        }
    ulocal32(r0, r1, i0, 64);
    #pragma unroll
    for (int j = 16; j >= 1; j >>= 1) {
        r0 = ushfl(r0, i0, j, 64);
        r1 = ushfl(r1, i1, j, 64);
    }
    #pragma unroll
    for (int k = 128; k <= CAP; k <<= 1) {
        sm->u.s[i0] = r0; sm->u.s[i1] = r1;
        __syncthreads();
        #pragma unroll
        for (int j = k >> 1; j >= 64; j >>= 1) {
            const unsigned long long o0 = sm->u.s[i0 ^ j];
            const unsigned long long o1 = sm->u.s[i1 ^ j];
            r0 = upick(r0, o0, i0, j, k);
            r1 = upick(r1, o1, i1, j, k);
            __syncthreads();                       // all reads done
            if (j > 64) { sm->u.s[i0] = r0; sm->u.s[i1] = r1; __syncthreads(); }
        }
        ulocal32(r0, r1, i0, k);
        #pragma unroll
        for (int j = 16; j >= 1; j >>= 1) {
            r0 = ushfl(r0, i0, j, k);
            r1 = ushfl(r1, i1, j, k);
        }
    }

    // ---- epilogue: slots < 300 decode, boxes from smem ----
    const float fx = (float)sizes[1];
    const float fy = (float)sizes[0];
    #pragma unroll
    for (int e = 0; e < 2; e++) {
        const int slot = e ? i1 : i0;
        if (slot < TOPK) {
            const unsigned long long pk = e ? r1 : r0;
            const unsigned key  = (unsigned)(pk >> 32);
            const unsigned flat = 0xFFFFFFFFu - (unsigned)(pk & 0xFFFFFFFFu);
            const float lv    = key2f(key);
            const float score = 1.0f / (1.0f + __expf(-lv));
            const unsigned q   = flat / (unsigned)NCLS;
            const unsigned lbl = flat - q * (unsigned)NCLS;
            const float4 b = sbx[q];                       // [cx, cy, w, h]
            float2* o = reinterpret_cast<float2*>(out + ((size_t)n * TOPK + slot) * 6);
            o[0] = make_float2((float)lbl, score);
            o[1] = make_float2((b.x - 0.5f * b.z) * fx, (b.y - 0.5f * b.w) * fy);
            o[2] = make_float2(b.z * fx, b.w * fy);
        }
    }
}

// ---- persistent fused kernel: stream all own segments, then sort ----
__global__ __launch_bounds__(SCTA, 3)
void scan_rank(const float4* __restrict__ lg,
               const float4* __restrict__ bx,
               const int*    __restrict__ sizes,
               float*        __restrict__ out)
{
    __shared__ SortSmem sm;
    __shared__ float4 sbx[NQ];          // 16KB: prefetched boxes (sorters)

    const int bid = blockIdx.x;
    const int t   = threadIdx.x;

    // ========== phase 1: stream segments bid, bid+G, ... ==========
    for (unsigned sid = (unsigned)bid; sid < (unsigned)NSEG; sid += gridDim.x) {
        const unsigned n   = sid >> 3;
        const unsigned seg = sid & 7u;
        const unsigned f4base = n * (unsigned)NF4B + seg * (unsigned)SEGF4;

        if (t == 0) sm.c = 0;
        __syncthreads();

        // 2500 = 4*512 + 452 : 4 full strides + partial 5th
        float4 v[5];
        #pragma unroll
        for (int k = 0; k < 4; k++) v[k] = lg[f4base + t + k * SCTA];
        const bool has5 = (t < (int)(SEGF4 - 4 * SCTA));   // t < 452
        if (has5) v[4] = lg[f4base + t + 4 * SCTA];

        #pragma unroll
        for (int k = 0; k < 5; k++) {
            if (k == 4 && !has5) continue;
            const float4 x = v[k];
            if (fmaxf(fmaxf(x.x, x.y), fmaxf(x.z, x.w)) > THR) {  // ~2%
                const unsigned loc0 = (seg * (unsigned)SEGF4 + (unsigned)t + (unsigned)k * SCTA) * 4u;
                if (x.x > THR) { int p = atomicAdd(&sm.c, 1); if (p < BUFCAP) sm.u.s[p] = pack(x.x, loc0 + 0u); }
                if (x.y > THR) { int p = atomicAdd(&sm.c, 1); if (p < BUFCAP) sm.u.s[p] = pack(x.y, loc0 + 1u); }
                if (x.z > THR) { int p = atomicAdd(&sm.c, 1); if (p < BUFCAP) sm.u.s[p] = pack(x.z, loc0 + 2u); }
                if (x.w > THR) { int p = atomicAdd(&sm.c, 1); if (p < BUFCAP) sm.u.s[p] = pack(x.w, loc0 + 3u); }
            }
        }
        __syncthreads();

        const int cnt = sm.c;
        if (t == 0) {
            if (cnt > BUFCAP) {       // overflow -> poison count, force fallback
                atomicAdd(&g_cnt[n * GPAD], 1000000);
                sm.base = -1;
            } else {
                sm.base = atomicAdd(&g_cnt[n * GPAD], cnt);
            }
        }
        __syncthreads();

        const int base = sm.base;
        if (base >= 0) {
            for (int i = t; i < cnt; i += SCTA) {
                const int p = base + i;
                if (p < CAP) g_cand[n][p] = sm.u.s[i];   // >CAP -> fallback
            }
        }

        __syncthreads();                          // flush issued (+ sm reuse)
        if (t == 0)
            done_release_add(&g_done[n * GPAD]);  // publish + signal (no MEMBAR)
    }

    // ========== phase 2: CTAs 0..255 sort their batch ==========
    if (bid >= NB) return;
    const int n = bid;

    // prefetch boxes (independent of candidates; overlaps the poll)
    for (int i = t; i < NQ; i += SCTA)
        sbx[i] = bx[(size_t)n * NQ + i];

    if (t == 0) {
        while (done_acquire_ld(&g_done[n * GPAD]) < SEGS)
            __nanosleep(64);
    }
    __syncthreads();                              // all 512 still active here
    if (t >= RT) return;                          // sort uses 256 threads

    rank_body(&sm, sbx, lg, sizes, out, n, t);
}

// ================= generic-shape pipeline =================

__global__ __launch_bounds__(SCTA)
void scan_generic(const float4* __restrict__ lg, int total_f4)
{
    const unsigned S = gridDim.x * (unsigned)SCTA;
    for (unsigned i = blockIdx.x * SCTA + threadIdx.x; i < (unsigned)total_f4; i += S) {
        const float4 x = lg[i];
        if (fmaxf(fmaxf(x.x, x.y), fmaxf(x.z, x.w)) > THR) {
            const float e[4] = {x.x, x.y, x.z, x.w};
            #pragma unroll
            for (int j = 0; j < 4; j++) {
                if (e[j] > THR) {
                    const unsigned flat = i * 4u + (unsigned)j;
                    const unsigned n    = flat / (unsigned)NPB;
                    if (n < (unsigned)NB) {
                        const int p = atomicAdd(&g_cnt[n * GPAD], 1);
                        if (p < CAP)
                            g_cand[n][p] = pack(e[j], flat - n * (unsigned)NPB);
                    }
                }
            }
        }
    }
}

__global__ __launch_bounds__(RT)
void rank_kernel(const float4* __restrict__ lg,
                 const float4* __restrict__ bx,
                 const int*    __restrict__ sizes,
                 float*        __restrict__ out)
{
    __shared__ SortSmem sm;
    __shared__ float4 sbx[NQ];
    const int n = blockIdx.x;
    for (int i = threadIdx.x; i < NQ; i += RT)
        sbx[i] = bx[(size_t)n * NQ + i];
    __syncthreads();
    rank_body(&sm, sbx, lg, sizes, out, n, threadIdx.x);
}

extern "C" void kernel_launch(void* const* d_in, const int* in_sizes, int n_in,
                              void* d_out, int out_size)
{
    const float* logits = (const float*)d_in[0];
    const float* boxes  = (const float*)d_in[1];
    const int*   sizes  = (const int*)d_in[2];
    const int total     = in_sizes[0];
    const int N         = total / NPB;

    if (total == NB * NPB) {
        scan_rank<<<GRID_P, SCTA>>>((const float4*)logits,
                                    (const float4*)boxes, sizes,
                                    (float*)d_out);
    } else {
        const int total_f4 = total / 4;
        int grid = (total_f4 + SCTA - 1) / SCTA;
        if (grid > 2048) grid = 2048;
        if (grid < 1) grid = 1;
        scan_generic<<<grid, SCTA>>>((const float4*)logits, total_f4);
        rank_kernel<<<N, RT>>>((const float4*)logits, (const float4*)boxes,
                               sizes, (float*)d_out);
    }
}